// round 2
// baseline (speedup 1.0000x reference)
#include <cuda_runtime.h>
#include <cstdint>

#define ZB 2
#define NPTS 4096
#define KNN 30
#define EDIM 256
#define DMODEL 128
#define NEDGE (ZB*NPTS*KNN)
#define TILE_E 128
#define KST 132               // EsT row stride (floats), k-major
#define WST 132               // W tile row stride

typedef unsigned long long ull;

__device__ int   g_Kidx[NEDGE];
__device__ float g_g1[DMODEL];
__device__ float g_c0[DMODEL];

__device__ __forceinline__ void fma2(ull &d, ull a, ull b) {
    asm("fma.rn.f32x2 %0, %1, %2, %0;" : "+l"(d) : "l"(a), "l"(b));
}
__device__ __forceinline__ ull pack2(float x, float y) {
    ull r; asm("mov.b64 %0, {%1, %2};" : "=l"(r) : "f"(x), "f"(y)); return r;
}
__device__ __forceinline__ void unpack2(float &x, float &y, ull v) {
    asm("mov.b64 {%0, %1}, %2;" : "=f"(x), "=f"(y) : "l"(v));
}

// --------------------------------------------------------------------------
__global__ void prep_kernel(const float* __restrict__ W, const float* __restrict__ gamma,
                            const float* __restrict__ beta, const float* __restrict__ bias) {
    int o = threadIdx.x;
    float a1 = 0.f, a0 = 0.f;
    for (int r = 0; r < EDIM; ++r) {
        float w = W[r*DMODEL + o];
        a1 = fmaf(gamma[r], w, a1);
        a0 = fmaf(beta[r],  w, a0);
    }
    g_g1[o] = a1;
    g_c0[o] = a0 + bias[o];
}

// --------------------------------------------------------------------------
__global__ __launch_bounds__(256) void knn_kernel(
        const float* __restrict__ C, const unsigned char* __restrict__ nmask,
        float* __restrict__ koutf, float* __restrict__ moutf) {
    extern __shared__ float sh[];
    float* xs = sh; float* ys = sh + NPTS; float* zs = sh + 2*NPTS;
    int z = blockIdx.x >> 9;
    int rowbase = (blockIdx.x & 511) * 8;
    const float* Cz = C + (size_t)z*NPTS*12;
    for (int t = threadIdx.x; t < NPTS; t += blockDim.x) {
        const float* p = Cz + t*12 + 3;   // atom 1 = Ca
        xs[t] = p[0]; ys[t] = p[1]; zs[t] = p[2];
    }
    __syncthreads();
    int w = threadIdx.x >> 5, lane = threadIdx.x & 31;
    int i = rowbase + w;
    float qx = xs[i], qy = ys[i], qz = zs[i];

    ull keys[KNN];
#pragma unroll
    for (int t = 0; t < KNN; ++t) keys[t] = ~0ull;

    for (int c = lane; c < NPTS; c += 32) {
        float dx = __fsub_rn(xs[c], qx);
        float dy = __fsub_rn(ys[c], qy);
        float dz = __fsub_rn(zs[c], qz);
        float sq = __fadd_rn(__fadd_rn(__fmul_rn(dx,dx), __fmul_rn(dy,dy)), __fmul_rn(dz,dz));
        if (sq != 0.0f && nmask[z*NPTS + c] == 0) {
            ull key = ((ull)__float_as_uint(sq) << 32) | (unsigned)c;
            if (key < keys[KNN-1]) {
                keys[KNN-1] = key;
#pragma unroll
                for (int t = KNN-1; t > 0; --t) {
                    if (keys[t] < keys[t-1]) { ull tmp = keys[t-1]; keys[t-1] = keys[t]; keys[t] = tmp; }
                    else break;
                }
            }
        }
    }
    // merge 32 sorted lists -> global ascending top-30
    ull my = keys[0];
    ull mine = ~0ull;
    for (int t = 0; t < KNN; ++t) {
        ull m = my;
#pragma unroll
        for (int o = 16; o; o >>= 1) {
            ull v = __shfl_xor_sync(0xffffffffu, m, o);
            m = (v < m) ? v : m;
        }
        if (my == m) {
#pragma unroll
            for (int u = 0; u < KNN-1; ++u) keys[u] = keys[u+1];
            keys[KNN-1] = ~0ull;
            my = keys[0];
        }
        if (lane == t) mine = m;
    }
    if (lane < KNN) {
        float sq = __uint_as_float((unsigned)(mine >> 32));
        int j = (int)(unsigned)(mine & 0xffffffffu);
        bool mask = (nmask[z*NPTS + i] == 0) && (nmask[z*NPTS + j] == 0)
                    && (sq != 0.f) && (sq < 144.f);
        int kf = mask ? j : i;
        int eidx = (z*NPTS + i)*KNN + lane;
        g_Kidx[eidx] = kf;
        koutf[eidx] = (float)kf;
        moutf[eidx] = mask ? 1.f : 0.f;
    }
}

// --------------------------------------------------------------------------
// 128 edges per block. Phase A: RBF features (3 exps/distance via anchored
// geometric recurrence) * gamma -> EsT (k-major) + LN stats.
// Phase B: 128x128 fp32 GEMM (K=256), f32x2 FMA, LN folded into epilogue.
__global__ __launch_bounds__(256, 1) void edge_kernel(
        const float* __restrict__ C, const float* __restrict__ centers,
        const float* __restrict__ gamma, const float* __restrict__ W,
        float* __restrict__ Eout) {
    extern __shared__ float sh[];
    float* EsT = sh;                       // EDIM * KST
    float* Wt  = EsT + EDIM*KST;           // 32 * WST
    float* gs  = Wt + 32*WST;              // EDIM
    float* mus = gs + EDIM;                // TILE_E
    float* rsg = mus + TILE_E;             // TILE_E

    int tid = threadIdx.x;
    for (int t = tid; t < EDIM; t += blockDim.x) gs[t] = gamma[t];

    // ---- Phase A: 2 threads/edge; thread 'sub' handles query atoms {2sub, 2sub+1}
    int eL = tid >> 1, sub = tid & 1;
    int e = blockIdx.x*TILE_E + eL;
    int z = e / (NPTS*KNN);
    int i = (e - z*(NPTS*KNN)) / KNN;
    int j = g_Kidx[e];
    const float* Cz = C + (size_t)z*NPTS*12;
    float ci[6], cj[12];
    const float* pi = Cz + i*12 + sub*6;
#pragma unroll
    for (int t = 0; t < 6; ++t) ci[t] = pi[t];
    const float* pj = Cz + j*12;
#pragma unroll
    for (int t = 0; t < 12; ++t) cj[t] = pj[t];

    float c0c = centers[0];
    float delta = (centers[15] - c0c) * (1.f/15.f);
    float invS2 = 0.64f;                     // 1/1.25^2
    float invdelta = __fdividef(1.f, delta);
    float sconst = __expf(-2.f*delta*delta*invS2);

    __syncthreads();   // gs ready

    float sum = 0.f, ssq = 0.f;
#pragma unroll
    for (int ai = 0; ai < 2; ++ai) {
        float ax = ci[ai*3+0], ay = ci[ai*3+1], az = ci[ai*3+2];
        int fa = (sub*2 + ai)*64;
#pragma unroll
        for (int b = 0; b < 4; ++b) {
            float dx = ax - cj[b*3+0], dy = ay - cj[b*3+1], dz = az - cj[b*3+2];
            float dsq = dx*dx + dy*dy + dz*dz;
            float d = sqrtf(dsq);
            int m = __float2int_rn((d - c0c) * invdelta);
            m = m < 0 ? 0 : (m > 15 ? 15 : m);
            float u = d - fmaf((float)m, delta, c0c);
            float vm = __expf(-u*u*invS2);
            float g  = __expf((2.f*delta*u - delta*delta)*invS2);
            float h  = __fdividef(sconst, g);
            int fb = fa + b*16;
            EsT[(fb+m)*KST + eL] = vm * gs[fb+m];
            sum += vm; ssq = fmaf(vm, vm, ssq);
            float v = vm, rat = g;
            for (int r = m+1; r < 16; ++r) {
                v *= rat; rat *= sconst;
                EsT[(fb+r)*KST + eL] = v * gs[fb+r];
                sum += v; ssq = fmaf(v, v, ssq);
            }
            v = vm; rat = h;
            for (int r = m-1; r >= 0; --r) {
                v *= rat; rat *= sconst;
                EsT[(fb+r)*KST + eL] = v * gs[fb+r];
                sum += v; ssq = fmaf(v, v, ssq);
            }
        }
    }
    sum += __shfl_xor_sync(0xffffffffu, sum, 1);
    ssq += __shfl_xor_sync(0xffffffffu, ssq, 1);
    if (sub == 0) {
        float mu = sum * (1.f/256.f);
        float var = ssq * (1.f/256.f) - mu*mu;
        mus[eL] = mu;
        rsg[eL] = rsqrtf(var + 1e-5f);
    }
    __syncthreads();

    // ---- Phase B: 8x8 micro-tile per thread, 16x16 thread grid
    int ty = tid >> 4, tx = tid & 15;
    ull acc[8][4];
#pragma unroll
    for (int r = 0; r < 8; ++r)
#pragma unroll
        for (int c = 0; c < 4; ++c) acc[r][c] = 0ull;

    int wr = tid >> 3, wc = (tid & 7) * 16;
    for (int kt = 0; kt < 8; ++kt) {
        const float4* wsrc = (const float4*)(W + (size_t)(kt*32 + wr)*DMODEL + wc);
        float4 w0 = wsrc[0], w1 = wsrc[1], w2 = wsrc[2], w3 = wsrc[3];
        if (kt) __syncthreads();
        float4* wdst = (float4*)(Wt + wr*WST + wc);
        wdst[0] = w0; wdst[1] = w1; wdst[2] = w2; wdst[3] = w3;
        __syncthreads();
#pragma unroll 4
        for (int kk = 0; kk < 32; ++kk) {
            const float* ap = EsT + (kt*32 + kk)*KST + ty*8;
            float4 a0 = *(const float4*)ap;
            float4 a1 = *(const float4*)(ap + 4);
            const ull* bp = (const ull*)(Wt + kk*WST + tx*8);
            ull b0 = bp[0], b1 = bp[1], b2 = bp[2], b3 = bp[3];
            ull ad[8];
            ad[0]=pack2(a0.x,a0.x); ad[1]=pack2(a0.y,a0.y);
            ad[2]=pack2(a0.z,a0.z); ad[3]=pack2(a0.w,a0.w);
            ad[4]=pack2(a1.x,a1.x); ad[5]=pack2(a1.y,a1.y);
            ad[6]=pack2(a1.z,a1.z); ad[7]=pack2(a1.w,a1.w);
#pragma unroll
            for (int r = 0; r < 8; ++r) {
                fma2(acc[r][0], ad[r], b0);
                fma2(acc[r][1], ad[r], b1);
                fma2(acc[r][2], ad[r], b2);
                fma2(acc[r][3], ad[r], b3);
            }
        }
    }

    // ---- epilogue: out = rsig*(acc - mu*g1) + c0
    float g1v[8], c0v[8];
#pragma unroll
    for (int c = 0; c < 8; ++c) { g1v[c] = g_g1[tx*8+c]; c0v[c] = g_c0[tx*8+c]; }
#pragma unroll
    for (int r = 0; r < 8; ++r) {
        int row = ty*8 + r;
        float mu = mus[row], rs = rsg[row];
        float v[8];
#pragma unroll
        for (int c = 0; c < 4; ++c) unpack2(v[2*c], v[2*c+1], acc[r][c]);
        float o[8];
#pragma unroll
        for (int c = 0; c < 8; ++c)
            o[c] = fmaf(rs, fmaf(-mu, g1v[c], v[c]), c0v[c]);
        float* op = Eout + (size_t)(blockIdx.x*TILE_E + row)*DMODEL + tx*8;
        ((float4*)op)[0] = make_float4(o[0],o[1],o[2],o[3]);
        ((float4*)op)[1] = make_float4(o[4],o[5],o[6],o[7]);
    }
}

// --------------------------------------------------------------------------
extern "C" void kernel_launch(void* const* d_in, const int* in_sizes, int n_in,
                              void* d_out, int out_size) {
    const float* C       = (const float*)d_in[0];
    const unsigned char* nm = (const unsigned char*)d_in[1];
    const float* centers = (const float*)d_in[2];
    const float* gamma   = (const float*)d_in[3];
    const float* beta    = (const float*)d_in[4];
    const float* W       = (const float*)d_in[5];
    const float* bias    = (const float*)d_in[6];
    float* out = (float*)d_out;
    float* kout = out + (size_t)NEDGE*DMODEL;   // Kidx as float
    float* mout = kout + NEDGE;                 // edge_mask as float

    static bool attr_done = false;
    if (!attr_done) {
        cudaFuncSetAttribute(edge_kernel, cudaFuncAttributeMaxDynamicSharedMemorySize, 200*1024);
        cudaFuncSetAttribute(knn_kernel,  cudaFuncAttributeMaxDynamicSharedMemorySize, 64*1024);
        attr_done = true;
    }

    prep_kernel<<<1, DMODEL>>>(W, gamma, beta, bias);
    knn_kernel<<<ZB*(NPTS/8), 256, 3*NPTS*4>>>(C, nm, kout, mout);
    size_t esm = (size_t)(EDIM*KST + 32*WST + EDIM + 2*TILE_E) * 4;
    edge_kernel<<<NEDGE/TILE_E, 256, esm>>>(C, centers, gamma, W, out);
}

// round 4
// speedup vs baseline: 1.2140x; 1.2140x over previous
#include <cuda_runtime.h>
#include <cstdint>

#define ZB 2
#define NPTS 4096
#define KNN 30
#define EDIM 256
#define DMODEL 128
#define NEDGE (ZB*NPTS*KNN)
#define ASTRIDE 264

typedef unsigned long long ull;

__device__ int    g_Kidx[NEDGE];
__device__ float  g_g1[DMODEL];
__device__ float  g_c0[DMODEL];
__device__ float2 g_Bfrag[32*16*32];   // [kstep][nfrag][lane] -> (b0,b1)

__device__ __forceinline__ void mma8(float c[4], uint32_t a0, uint32_t a1, uint32_t a2, uint32_t a3,
                                     uint32_t b0, uint32_t b1) {
    asm("mma.sync.aligned.m16n8k8.row.col.f32.tf32.tf32.f32 "
        "{%0,%1,%2,%3},{%4,%5,%6,%7},{%8,%9},{%0,%1,%2,%3};"
        : "+f"(c[0]), "+f"(c[1]), "+f"(c[2]), "+f"(c[3])
        : "r"(a0), "r"(a1), "r"(a2), "r"(a3), "r"(b0), "r"(b1));
}

// --------------------------------------------------------------------------
// grid 9: blocks 0-7 fill g_Bfrag (fragment-ordered gamma.*W), block 8 -> g1/c0
__global__ __launch_bounds__(1024) void prep_kernel(
        const float* __restrict__ W, const float* __restrict__ gamma,
        const float* __restrict__ beta, const float* __restrict__ bias) {
    int tid = threadIdx.x;
    if (blockIdx.x < 8) {
#pragma unroll
        for (int u = 0; u < 2; ++u) {
            int p = blockIdx.x*2048 + u*1024 + tid;       // 0..16383
            int lane = p & 31, nf = (p >> 5) & 15, ks8 = p >> 9;
            int n = nf*8 + (lane >> 2);
            float2 v;
#pragma unroll
            for (int h = 0; h < 2; ++h) {
                int t = (lane & 3) + 4*h;                 // mma-local k
                int ksA = ks8*8 + t;                      // r*16+pair coordinate
                int kL = (ksA & 15)*16 + (ksA >> 4);      // logical feature row
                float w = W[(size_t)kL*DMODEL + n] * gamma[kL];
                if (h == 0) v.x = w; else v.y = w;
            }
            g_Bfrag[p] = v;
        }
    } else {
        __shared__ float p1[8][DMODEL], p0[8][DMODEL];
        int g = tid >> 7, o = tid & 127;
        float a1 = 0.f, a0 = 0.f;
        int rb = g*32;
#pragma unroll 8
        for (int rr = 0; rr < 32; ++rr) {
            float w = W[(size_t)(rb+rr)*DMODEL + o];
            a1 = fmaf(gamma[rb+rr], w, a1);
            a0 = fmaf(beta[rb+rr],  w, a0);
        }
        p1[g][o] = a1; p0[g][o] = a0;
        __syncthreads();
        if (g == 0) {
            float s1 = 0.f, s0 = 0.f;
#pragma unroll
            for (int k = 0; k < 8; ++k) { s1 += p1[k][o]; s0 += p0[k][o]; }
            g_g1[o] = s1;
            g_c0[o] = s0 + bias[o];
        }
    }
}

// --------------------------------------------------------------------------
__global__ __launch_bounds__(256) void knn_kernel(
        const float* __restrict__ C, const unsigned char* __restrict__ nmask,
        float* __restrict__ koutf, float* __restrict__ moutf) {
    extern __shared__ float sh[];
    float* xs = sh; float* ys = sh + NPTS; float* zs = sh + 2*NPTS;
    int z = blockIdx.x >> 9;
    int rowbase = (blockIdx.x & 511) * 8;
    const float* Cz = C + (size_t)z*NPTS*12;
    for (int t = threadIdx.x; t < NPTS; t += blockDim.x) {
        const float* p = Cz + t*12 + 3;   // atom 1 = Ca
        xs[t] = p[0]; ys[t] = p[1]; zs[t] = p[2];
    }
    __syncthreads();
    int w = threadIdx.x >> 5, lane = threadIdx.x & 31;
    int i = rowbase + w;
    float qx = xs[i], qy = ys[i], qz = zs[i];

    ull keys[KNN];
#pragma unroll
    for (int t = 0; t < KNN; ++t) keys[t] = ~0ull;

    for (int c = lane; c < NPTS; c += 32) {
        float dx = __fsub_rn(xs[c], qx);
        float dy = __fsub_rn(ys[c], qy);
        float dz = __fsub_rn(zs[c], qz);
        float sq = __fadd_rn(__fadd_rn(__fmul_rn(dx,dx), __fmul_rn(dy,dy)), __fmul_rn(dz,dz));
        if (sq != 0.0f && nmask[z*NPTS + c] == 0) {
            ull key = ((ull)__float_as_uint(sq) << 32) | (unsigned)c;
            if (key < keys[KNN-1]) {
                keys[KNN-1] = key;
#pragma unroll
                for (int t = KNN-1; t > 0; --t) {
                    if (keys[t] < keys[t-1]) { ull tmp = keys[t-1]; keys[t-1] = keys[t]; keys[t] = tmp; }
                    else break;
                }
            }
        }
    }
    ull my = keys[0];
    ull mine = ~0ull;
    for (int t = 0; t < KNN; ++t) {
        ull m = my;
#pragma unroll
        for (int o = 16; o; o >>= 1) {
            ull v = __shfl_xor_sync(0xffffffffu, m, o);
            m = (v < m) ? v : m;
        }
        if (my == m) {
#pragma unroll
            for (int u = 0; u < KNN-1; ++u) keys[u] = keys[u+1];
            keys[KNN-1] = ~0ull;
            my = keys[0];
        }
        if (lane == t) mine = m;
    }
    if (lane < KNN) {
        float sq = __uint_as_float((unsigned)(mine >> 32));
        int j = (int)(unsigned)(mine & 0xffffffffu);
        bool mask = (nmask[z*NPTS + i] == 0) && (nmask[z*NPTS + j] == 0)
                    && (sq != 0.f) && (sq < 144.f);
        int kf = mask ? j : i;
        int eidx = (z*NPTS + i)*KNN + lane;
        g_Kidx[eidx] = kf;
        koutf[eidx] = (float)kf;
        moutf[eidx] = mask ? 1.f : 0.f;
    }
}

// --------------------------------------------------------------------------
// 512 threads, 128 edges/block. Phase A: raw RBF (geometric recurrence,
// 3 exps/dist) written K-permuted into smem A + LN stats. Phase B: tf32
// mma.sync 128x128x256, B frags streamed from g_Bfrag, LN epilogue.
__global__ __launch_bounds__(512, 1) void edge_kernel(
        const float* __restrict__ C, const float* __restrict__ centers,
        float* __restrict__ Eout) {
    extern __shared__ float As[];                 // 128*ASTRIDE
    float* g1s = As + 128*ASTRIDE;                // 128
    float* c0s = g1s + 128;
    float* mus = c0s + 128;
    float* rsg = mus + 128;

    int tid = threadIdx.x;
    if (tid < 128) { g1s[tid] = g_g1[tid]; c0s[tid] = g_c0[tid]; }

    float c0c = __ldg(centers), c15 = __ldg(centers + 15);
    float delta = (c15 - c0c) * (1.f/15.f);
    const float invS2 = 0.64f;
    float invdelta = __fdividef(1.f, delta);
    float sconst = __expf(-2.f*delta*delta*invS2);

    // ---- Phase A: 4 threads/edge; thread q handles query atom q (4 dists)
    {
        int m = tid >> 2, q = tid & 3;
        int e = blockIdx.x*128 + m;
        int z = e / (NPTS*KNN);
        int i = (e - z*(NPTS*KNN)) / KNN;
        int j = g_Kidx[e];
        const float* Cz = C + (size_t)z*NPTS*12;
        float ax = Cz[i*12 + q*3], ay = Cz[i*12 + q*3 + 1], az = Cz[i*12 + q*3 + 2];
        float cj[12];
#pragma unroll
        for (int t = 0; t < 12; ++t) cj[t] = Cz[j*12 + t];
        float* Arow = As + m*ASTRIDE;
        int pb0 = 8*(q >> 1) + (q & 1);
        float sum = 0.f, ssq = 0.f;
#pragma unroll
        for (int b = 0; b < 4; ++b) {
            int pbase = pb0 + 2*b;
            float dx = ax - cj[b*3+0], dy = ay - cj[b*3+1], dz = az - cj[b*3+2];
            float dsq = dx*dx + dy*dy + dz*dz;
            float d = sqrtf(dsq);
            int mi = __float2int_rn((d - c0c) * invdelta);
            mi = mi < 0 ? 0 : (mi > 15 ? 15 : mi);
            float u = d - fmaf((float)mi, delta, c0c);
            float vm = __expf(-u*u*invS2);
            float gup = __expf((2.f*delta*u - delta*delta)*invS2);
            float hdn = __fdividef(sconst, gup);
            Arow[mi*16 + pbase] = vm;
            sum += vm; ssq = fmaf(vm, vm, ssq);
            float v = vm, rat = gup;
            for (int r = mi+1; r < 16; ++r) {
                v *= rat; rat *= sconst;
                Arow[r*16 + pbase] = v;
                sum += v; ssq = fmaf(v, v, ssq);
            }
            v = vm; rat = hdn;
            for (int r = mi-1; r >= 0; --r) {
                v *= rat; rat *= sconst;
                Arow[r*16 + pbase] = v;
                sum += v; ssq = fmaf(v, v, ssq);
            }
        }
        sum += __shfl_xor_sync(0xffffffffu, sum, 1);
        ssq += __shfl_xor_sync(0xffffffffu, ssq, 1);
        sum += __shfl_xor_sync(0xffffffffu, sum, 2);
        ssq += __shfl_xor_sync(0xffffffffu, ssq, 2);
        if (q == 0) {
            float mu = sum * (1.f/256.f);
            float var = ssq * (1.f/256.f) - mu*mu;
            mus[m] = mu;
            rsg[m] = rsqrtf(var + 1e-5f);
        }
    }
    __syncthreads();

    // ---- Phase B: 16 warps = 4(M) x 4(N), warp tile 32x32
    int lane = tid & 31, wid = tid >> 5;
    int rowb = (wid >> 2)*32, nwid = wid & 3;
    int t4 = lane & 3, g4 = lane >> 2;
    float acc[2][4][4];
#pragma unroll
    for (int mf = 0; mf < 2; ++mf)
#pragma unroll
        for (int nf = 0; nf < 4; ++nf)
#pragma unroll
            for (int v = 0; v < 4; ++v) acc[mf][nf][v] = 0.f;

#pragma unroll 4
    for (int ks8 = 0; ks8 < 32; ++ks8) {
        float2 bf[4];
#pragma unroll
        for (int nf = 0; nf < 4; ++nf)
            bf[nf] = __ldg(&g_Bfrag[(ks8*16 + nwid*4 + nf)*32 + lane]);
#pragma unroll
        for (int mf = 0; mf < 2; ++mf) {
            int r0 = rowb + mf*16 + g4;
            float2 alo = *(const float2*)&As[r0*ASTRIDE + ks8*8 + 2*t4];
            float2 ahi = *(const float2*)&As[(r0+8)*ASTRIDE + ks8*8 + 2*t4];
            uint32_t a0 = __float_as_uint(alo.x), a2 = __float_as_uint(alo.y);
            uint32_t a1 = __float_as_uint(ahi.x), a3 = __float_as_uint(ahi.y);
#pragma unroll
            for (int nf = 0; nf < 4; ++nf)
                mma8(acc[mf][nf], a0, a1, a2, a3,
                     __float_as_uint(bf[nf].x), __float_as_uint(bf[nf].y));
        }
    }

    // ---- epilogue: out = rs*(acc - mu*g1) + c0
#pragma unroll
    for (int mf = 0; mf < 2; ++mf) {
        int r0 = rowb + mf*16 + g4;
        float mu0 = mus[r0],   rs0 = rsg[r0];
        float mu1 = mus[r0+8], rs1 = rsg[r0+8];
        float* o0 = Eout + ((size_t)(blockIdx.x*128 + r0))*DMODEL;
        float* o1 = o0 + 8*DMODEL;
#pragma unroll
        for (int nf = 0; nf < 4; ++nf) {
            int col = nwid*32 + nf*8 + 2*t4;
            float ga = g1s[col], gb = g1s[col+1];
            float ca = c0s[col], cb = c0s[col+1];
            float2 v0, v1;
            v0.x = fmaf(rs0, fmaf(-mu0, ga, acc[mf][nf][0]), ca);
            v0.y = fmaf(rs0, fmaf(-mu0, gb, acc[mf][nf][1]), cb);
            v1.x = fmaf(rs1, fmaf(-mu1, ga, acc[mf][nf][2]), ca);
            v1.y = fmaf(rs1, fmaf(-mu1, gb, acc[mf][nf][3]), cb);
            *(float2*)(o0 + col) = v0;
            *(float2*)(o1 + col) = v1;
        }
    }
}

// --------------------------------------------------------------------------
extern "C" void kernel_launch(void* const* d_in, const int* in_sizes, int n_in,
                              void* d_out, int out_size) {
    const float* C       = (const float*)d_in[0];
    const unsigned char* nm = (const unsigned char*)d_in[1];
    const float* centers = (const float*)d_in[2];
    const float* gamma   = (const float*)d_in[3];
    const float* beta    = (const float*)d_in[4];
    const float* W       = (const float*)d_in[5];
    const float* bias    = (const float*)d_in[6];
    float* out = (float*)d_out;
    float* kout = out + (size_t)NEDGE*DMODEL;
    float* mout = kout + NEDGE;

    size_t esm = (size_t)(128*ASTRIDE + 4*128) * 4;
    static bool attr_done = false;
    if (!attr_done) {
        cudaFuncSetAttribute(edge_kernel, cudaFuncAttributeMaxDynamicSharedMemorySize, (int)esm);
        cudaFuncSetAttribute(knn_kernel,  cudaFuncAttributeMaxDynamicSharedMemorySize, 64*1024);
        attr_done = true;
    }

    knn_kernel<<<ZB*(NPTS/8), 256, 3*NPTS*4>>>(C, nm, kout, mout);
    prep_kernel<<<9, 1024>>>(W, gamma, beta, bias);
    edge_kernel<<<NEDGE/128, 512, esm>>>(C, centers, out);
}

// round 5
// speedup vs baseline: 10.6991x; 8.8134x over previous
#include <cuda_runtime.h>
#include <cstdint>

#define ZB 2
#define NPTS 4096
#define KNN 30
#define EDIM 256
#define DMODEL 128
#define NEDGE (ZB*NPTS*KNN)
#define ASTRIDE 264
#define KROWS 16

typedef unsigned long long ull;

__device__ int    g_Kidx[NEDGE];
__device__ float  g_g1[DMODEL];
__device__ float  g_c0[DMODEL];
__device__ float2 g_Bfrag[32*16*32];   // [kstep][nfrag][lane] -> (b0,b1)

__device__ __forceinline__ void mma8(float c[4], uint32_t a0, uint32_t a1, uint32_t a2, uint32_t a3,
                                     uint32_t b0, uint32_t b1) {
    asm("mma.sync.aligned.m16n8k8.row.col.f32.tf32.tf32.f32 "
        "{%0,%1,%2,%3},{%4,%5,%6,%7},{%8,%9},{%0,%1,%2,%3};"
        : "+f"(c[0]), "+f"(c[1]), "+f"(c[2]), "+f"(c[3])
        : "r"(a0), "r"(a1), "r"(a2), "r"(a3), "r"(b0), "r"(b1));
}

// --------------------------------------------------------------------------
// grid 9: blocks 0-7 fill g_Bfrag (fragment-ordered gamma.*W), block 8 -> g1/c0
__global__ __launch_bounds__(1024) void prep_kernel(
        const float* __restrict__ W, const float* __restrict__ gamma,
        const float* __restrict__ beta, const float* __restrict__ bias) {
    int tid = threadIdx.x;
    if (blockIdx.x < 8) {
#pragma unroll
        for (int u = 0; u < 2; ++u) {
            int p = blockIdx.x*2048 + u*1024 + tid;       // 0..16383
            int lane = p & 31, nf = (p >> 5) & 15, ks8 = p >> 9;
            int n = nf*8 + (lane >> 2);
            float2 v;
#pragma unroll
            for (int h = 0; h < 2; ++h) {
                int t = (lane & 3) + 4*h;                 // mma-local k
                int ksA = ks8*8 + t;                      // r*16+pair coordinate
                int kL = (ksA & 15)*16 + (ksA >> 4);      // logical feature row
                float w = W[(size_t)kL*DMODEL + n] * gamma[kL];
                if (h == 0) v.x = w; else v.y = w;
            }
            g_Bfrag[p] = v;
        }
    } else {
        __shared__ float p1[8][DMODEL], p0[8][DMODEL];
        int g = tid >> 7, o = tid & 127;
        float a1 = 0.f, a0 = 0.f;
        int rb = g*32;
#pragma unroll 8
        for (int rr = 0; rr < 32; ++rr) {
            float w = W[(size_t)(rb+rr)*DMODEL + o];
            a1 = fmaf(gamma[rb+rr], w, a1);
            a0 = fmaf(beta[rb+rr],  w, a0);
        }
        p1[g][o] = a1; p0[g][o] = a0;
        __syncthreads();
        if (g == 0) {
            float s1 = 0.f, s0 = 0.f;
#pragma unroll
            for (int k = 0; k < 8; ++k) { s1 += p1[k][o]; s0 += p0[k][o]; }
            g_g1[o] = s1;
            g_c0[o] = s0 + bias[o];
        }
    }
}

// --------------------------------------------------------------------------
// 1 warp per row. Warp-distributed top-30: lane L holds rank-L key.
// Inserts are warp-uniform O(1) shift-inserts -> no divergent serial chains.
__global__ __launch_bounds__(32*KROWS) void knn_kernel(
        const float* __restrict__ C, const unsigned char* __restrict__ nmask,
        float* __restrict__ koutf, float* __restrict__ moutf) {
    extern __shared__ float sh[];
    float* xs = sh; float* ys = sh + NPTS; float* zs = sh + 2*NPTS;
    unsigned char* ms = (unsigned char*)(sh + 3*NPTS);
    int z = blockIdx.x / (NPTS/KROWS);
    int rowbase = (blockIdx.x % (NPTS/KROWS)) * KROWS;
    const float4* Cz4 = (const float4*)(C + (size_t)z*NPTS*12);
    for (int p = threadIdx.x; p < NPTS; p += 32*KROWS) {
        float4 a = Cz4[3*p], b = Cz4[3*p + 1];
        xs[p] = a.w; ys[p] = b.x; zs[p] = b.y;   // Ca = floats 3,4,5
        ms[p] = nmask[z*NPTS + p];
    }
    __syncthreads();
    int w = threadIdx.x >> 5, lane = threadIdx.x & 31;
    int i = rowbase + w;
    float qx = xs[i], qy = ys[i], qz = zs[i];

    ull slot = ~0ull;       // lane L: rank-L smallest key (lanes 0..29 valid)
    ull thresh = ~0ull;     // current 30th-smallest

#pragma unroll 1
    for (int kb = 0; kb < NPTS/32; ++kb) {
        int c = kb*32 + lane;
        float dx = __fsub_rn(xs[c], qx);
        float dy = __fsub_rn(ys[c], qy);
        float dz = __fsub_rn(zs[c], qz);
        float sq = __fadd_rn(__fadd_rn(__fmul_rn(dx,dx), __fmul_rn(dy,dy)), __fmul_rn(dz,dz));
        bool ok = (sq != 0.0f) && (ms[c] == 0);
        ull key = ((ull)__float_as_uint(sq) << 32) | (unsigned)c;
        unsigned bal = __ballot_sync(0xffffffffu, ok && key < thresh);
        while (bal) {
            int s = __ffs(bal) - 1;
            bal &= bal - 1;
            ull kk = __shfl_sync(0xffffffffu, key, s);
            if (kk < thresh) {
                ull shv = __shfl_up_sync(0xffffffffu, slot, 1);
                if (lane == 0) shv = 0ull;
                if (slot > kk) slot = (shv > kk) ? shv : kk;
                thresh = __shfl_sync(0xffffffffu, slot, 29);
            }
        }
    }

    if (lane < KNN) {
        float sq = __uint_as_float((unsigned)(slot >> 32));
        int j = (int)(unsigned)(slot & 0xffffffffu);
        bool mask = (ms[i] == 0) && (ms[j] == 0) && (sq != 0.f) && (sq < 144.f);
        int kf = mask ? j : i;
        int eidx = (z*NPTS + i)*KNN + lane;
        g_Kidx[eidx] = kf;
        koutf[eidx] = (float)kf;
        moutf[eidx] = mask ? 1.f : 0.f;
    }
}

// --------------------------------------------------------------------------
// 512 threads, 128 edges/block. Phase A: raw RBF (geometric recurrence,
// 3 exps/dist) written K-permuted into smem A + LN stats. Phase B: tf32
// mma.sync 128x128x256, B frags streamed from g_Bfrag, LN epilogue.
__global__ __launch_bounds__(512, 1) void edge_kernel(
        const float* __restrict__ C, const float* __restrict__ centers,
        float* __restrict__ Eout) {
    extern __shared__ float As[];                 // 128*ASTRIDE
    float* g1s = As + 128*ASTRIDE;                // 128
    float* c0s = g1s + 128;
    float* mus = c0s + 128;
    float* rsg = mus + 128;

    int tid = threadIdx.x;
    if (tid < 128) { g1s[tid] = g_g1[tid]; c0s[tid] = g_c0[tid]; }

    float c0c = __ldg(centers), c15 = __ldg(centers + 15);
    float delta = (c15 - c0c) * (1.f/15.f);
    const float invS2 = 0.64f;
    float invdelta = __fdividef(1.f, delta);
    float sconst = __expf(-2.f*delta*delta*invS2);

    // ---- Phase A: 4 threads/edge; thread q handles query atom q (4 dists)
    {
        int m = tid >> 2, q = tid & 3;
        int e = blockIdx.x*128 + m;
        int z = e / (NPTS*KNN);
        int i = (e - z*(NPTS*KNN)) / KNN;
        int j = g_Kidx[e];
        const float* Cz = C + (size_t)z*NPTS*12;
        float ax = Cz[i*12 + q*3], ay = Cz[i*12 + q*3 + 1], az = Cz[i*12 + q*3 + 2];
        float cj[12];
#pragma unroll
        for (int t = 0; t < 12; ++t) cj[t] = Cz[j*12 + t];
        float* Arow = As + m*ASTRIDE;
        int pb0 = 8*(q >> 1) + (q & 1);
        float sum = 0.f, ssq = 0.f;
#pragma unroll
        for (int b = 0; b < 4; ++b) {
            int pbase = pb0 + 2*b;
            float dx = ax - cj[b*3+0], dy = ay - cj[b*3+1], dz = az - cj[b*3+2];
            float dsq = dx*dx + dy*dy + dz*dz;
            float d = sqrtf(dsq);
            int mi = __float2int_rn((d - c0c) * invdelta);
            mi = mi < 0 ? 0 : (mi > 15 ? 15 : mi);
            float u = d - fmaf((float)mi, delta, c0c);
            float vm = __expf(-u*u*invS2);
            float gup = __expf((2.f*delta*u - delta*delta)*invS2);
            float hdn = __fdividef(sconst, gup);
            Arow[mi*16 + pbase] = vm;
            sum += vm; ssq = fmaf(vm, vm, ssq);
            float v = vm, rat = gup;
            for (int r = mi+1; r < 16; ++r) {
                v *= rat; rat *= sconst;
                Arow[r*16 + pbase] = v;
                sum += v; ssq = fmaf(v, v, ssq);
            }
            v = vm; rat = hdn;
            for (int r = mi-1; r >= 0; --r) {
                v *= rat; rat *= sconst;
                Arow[r*16 + pbase] = v;
                sum += v; ssq = fmaf(v, v, ssq);
            }
        }
        sum += __shfl_xor_sync(0xffffffffu, sum, 1);
        ssq += __shfl_xor_sync(0xffffffffu, ssq, 1);
        sum += __shfl_xor_sync(0xffffffffu, sum, 2);
        ssq += __shfl_xor_sync(0xffffffffu, ssq, 2);
        if (q == 0) {
            float mu = sum * (1.f/256.f);
            float var = ssq * (1.f/256.f) - mu*mu;
            mus[m] = mu;
            rsg[m] = rsqrtf(var + 1e-5f);
        }
    }
    __syncthreads();

    // ---- Phase B: 16 warps = 4(M) x 4(N), warp tile 32x32
    int lane = tid & 31, wid = tid >> 5;
    int rowb = (wid >> 2)*32, nwid = wid & 3;
    int t4 = lane & 3, g4 = lane >> 2;
    float acc[2][4][4];
#pragma unroll
    for (int mf = 0; mf < 2; ++mf)
#pragma unroll
        for (int nf = 0; nf < 4; ++nf)
#pragma unroll
            for (int v = 0; v < 4; ++v) acc[mf][nf][v] = 0.f;

#pragma unroll 4
    for (int ks8 = 0; ks8 < 32; ++ks8) {
        float2 bf[4];
#pragma unroll
        for (int nf = 0; nf < 4; ++nf)
            bf[nf] = __ldg(&g_Bfrag[(ks8*16 + nwid*4 + nf)*32 + lane]);
#pragma unroll
        for (int mf = 0; mf < 2; ++mf) {
            int r0 = rowb + mf*16 + g4;
            float2 alo = *(const float2*)&As[r0*ASTRIDE + ks8*8 + 2*t4];
            float2 ahi = *(const float2*)&As[(r0+8)*ASTRIDE + ks8*8 + 2*t4];
            uint32_t a0 = __float_as_uint(alo.x), a2 = __float_as_uint(alo.y);
            uint32_t a1 = __float_as_uint(ahi.x), a3 = __float_as_uint(ahi.y);
#pragma unroll
            for (int nf = 0; nf < 4; ++nf)
                mma8(acc[mf][nf], a0, a1, a2, a3,
                     __float_as_uint(bf[nf].x), __float_as_uint(bf[nf].y));
        }
    }

    // ---- epilogue: out = rs*(acc - mu*g1) + c0
#pragma unroll
    for (int mf = 0; mf < 2; ++mf) {
        int r0 = rowb + mf*16 + g4;
        float mu0 = mus[r0],   rs0 = rsg[r0];
        float mu1 = mus[r0+8], rs1 = rsg[r0+8];
        float* o0 = Eout + ((size_t)(blockIdx.x*128 + r0))*DMODEL;
        float* o1 = o0 + 8*DMODEL;
#pragma unroll
        for (int nf = 0; nf < 4; ++nf) {
            int col = nwid*32 + nf*8 + 2*t4;
            float ga = g1s[col], gb = g1s[col+1];
            float ca = c0s[col], cb = c0s[col+1];
            float2 v0, v1;
            v0.x = fmaf(rs0, fmaf(-mu0, ga, acc[mf][nf][0]), ca);
            v0.y = fmaf(rs0, fmaf(-mu0, gb, acc[mf][nf][1]), cb);
            v1.x = fmaf(rs1, fmaf(-mu1, ga, acc[mf][nf][2]), ca);
            v1.y = fmaf(rs1, fmaf(-mu1, gb, acc[mf][nf][3]), cb);
            *(float2*)(o0 + col) = v0;
            *(float2*)(o1 + col) = v1;
        }
    }
}

// --------------------------------------------------------------------------
extern "C" void kernel_launch(void* const* d_in, const int* in_sizes, int n_in,
                              void* d_out, int out_size) {
    const float* C       = (const float*)d_in[0];
    const unsigned char* nm = (const unsigned char*)d_in[1];
    const float* centers = (const float*)d_in[2];
    const float* gamma   = (const float*)d_in[3];
    const float* beta    = (const float*)d_in[4];
    const float* W       = (const float*)d_in[5];
    const float* bias    = (const float*)d_in[6];
    float* out = (float*)d_out;
    float* kout = out + (size_t)NEDGE*DMODEL;
    float* mout = kout + NEDGE;

    size_t esm = (size_t)(128*ASTRIDE + 4*128) * 4;
    size_t ksm = (size_t)(3*NPTS*4 + NPTS);
    static bool attr_done = false;
    if (!attr_done) {
        cudaFuncSetAttribute(edge_kernel, cudaFuncAttributeMaxDynamicSharedMemorySize, (int)esm);
        cudaFuncSetAttribute(knn_kernel,  cudaFuncAttributeMaxDynamicSharedMemorySize, (int)ksm);
        attr_done = true;
    }

    knn_kernel<<<ZB*(NPTS/KROWS), 32*KROWS, ksm>>>(C, nm, kout, mout);
    prep_kernel<<<9, 1024>>>(W, gamma, beta, bias);
    edge_kernel<<<NEDGE/128, 512, esm>>>(C, centers, out);
}

// round 6
// speedup vs baseline: 11.3068x; 1.0568x over previous
#include <cuda_runtime.h>
#include <cstdint>

#define ZB 2
#define NPTS 4096
#define KNN 30
#define DMODEL 128
#define NEDGE (ZB*NPTS*KNN)
#define ASTR2 136
#define KROWS 16

typedef unsigned long long ull;

__device__ int    g_Kidx[NEDGE];
__device__ float  g_g1[DMODEL];
__device__ float  g_c0[DMODEL];
__device__ float2 g_Bfrag[32*16*32];   // [ks8][nfrag][lane] -> (b0,b1)

__device__ __forceinline__ void mma8(float c[4], uint32_t a0, uint32_t a1, uint32_t a2, uint32_t a3,
                                     uint32_t b0, uint32_t b1) {
    asm("mma.sync.aligned.m16n8k8.row.col.f32.tf32.tf32.f32 "
        "{%0,%1,%2,%3},{%4,%5,%6,%7},{%8,%9},{%0,%1,%2,%3};"
        : "+f"(c[0]), "+f"(c[1]), "+f"(c[2]), "+f"(c[3])
        : "r"(a0), "r"(a1), "r"(a2), "r"(a3), "r"(b0), "r"(b1));
}

// --------------------------------------------------------------------------
__global__ __launch_bounds__(1024) void prep_kernel(
        const float* __restrict__ W, const float* __restrict__ gamma,
        const float* __restrict__ beta, const float* __restrict__ bias) {
    int tid = threadIdx.x;
    if (blockIdx.x < 8) {
#pragma unroll
        for (int u = 0; u < 2; ++u) {
            int p = blockIdx.x*2048 + u*1024 + tid;       // 0..16383
            int lane = p & 31, nf = (p >> 5) & 15, ks8 = p >> 9;
            int n = nf*8 + (lane >> 2);
            float2 v;
#pragma unroll
            for (int h = 0; h < 2; ++h) {
                int t = (lane & 3) + 4*h;                 // mma-local k
                int ksA = ks8*8 + t;
                int kL = (ksA & 15)*16 + (ksA >> 4);      // logical feature row
                float w = W[(size_t)kL*DMODEL + n] * gamma[kL];
                if (h == 0) v.x = w; else v.y = w;
            }
            g_Bfrag[p] = v;
        }
    } else {
        __shared__ float p1[8][DMODEL], p0[8][DMODEL];
        int g = tid >> 7, o = tid & 127;
        float a1 = 0.f, a0 = 0.f;
        int rb = g*32;
#pragma unroll 8
        for (int rr = 0; rr < 32; ++rr) {
            float w = W[(size_t)(rb+rr)*DMODEL + o];
            a1 = fmaf(gamma[rb+rr], w, a1);
            a0 = fmaf(beta[rb+rr],  w, a0);
        }
        p1[g][o] = a1; p0[g][o] = a0;
        __syncthreads();
        if (g == 0) {
            float s1 = 0.f, s0 = 0.f;
#pragma unroll
            for (int k = 0; k < 8; ++k) { s1 += p1[k][o]; s0 += p0[k][o]; }
            g_g1[o] = s1;
            g_c0[o] = s0 + bias[o];
        }
    }
}

// --------------------------------------------------------------------------
// 1 warp/row, warp-distributed top-30. float4 staging (mask folded as NaN),
// float-threshold ballots, deferred threshold refresh, checkless inserts.
__global__ __launch_bounds__(32*KROWS) void knn_kernel(
        const float* __restrict__ C, const unsigned char* __restrict__ nmask,
        float* __restrict__ koutf, float* __restrict__ moutf) {
    extern __shared__ float4 sh4[];            // NPTS
    int z = blockIdx.x / (NPTS/KROWS);
    int rowbase = (blockIdx.x % (NPTS/KROWS)) * KROWS;
    const float4* Cz4 = (const float4*)(C + (size_t)z*NPTS*12);
    for (int p = threadIdx.x; p < NPTS; p += 32*KROWS) {
        float4 a = Cz4[3*p], b = Cz4[3*p + 1];     // Ca = floats 3,4,5
        float x = a.w;
        if (nmask[z*NPTS + p]) x = __int_as_float(0x7fffffff);   // NaN-fold mask
        sh4[p] = make_float4(x, b.x, b.y, 0.f);
    }
    __syncthreads();
    int w = threadIdx.x >> 5, lane = threadIdx.x & 31;
    int i = rowbase + w;
    float4 qv = sh4[i];
    float qx = qv.x, qy = qv.y, qz = qv.z;

    ull slot = ~0ull;                              // lane L: rank-L key
    float thr = __uint_as_float(0xFFFFFFFFu);      // NaN: !(sq>thr) passes all

#pragma unroll 1
    for (int kb = 0; kb < NPTS/64; ++kb) {
        int c0 = kb*64 + lane, c1 = c0 + 32;
        float4 p0 = sh4[c0], p1 = sh4[c1];
        float dx0 = __fsub_rn(p0.x, qx), dy0 = __fsub_rn(p0.y, qy), dz0 = __fsub_rn(p0.z, qz);
        float dx1 = __fsub_rn(p1.x, qx), dy1 = __fsub_rn(p1.y, qy), dz1 = __fsub_rn(p1.z, qz);
        float sq0 = __fadd_rn(__fadd_rn(__fmul_rn(dx0,dx0), __fmul_rn(dy0,dy0)), __fmul_rn(dz0,dz0));
        float sq1 = __fadd_rn(__fadd_rn(__fmul_rn(dx1,dx1), __fmul_rn(dy1,dy1)), __fmul_rn(dz1,dz1));
        unsigned bal0 = __ballot_sync(0xffffffffu, (sq0 > 0.f) && !(sq0 > thr));
        unsigned bal1 = __ballot_sync(0xffffffffu, (sq1 > 0.f) && !(sq1 > thr));
        if (bal0 | bal1) {
            ull key0 = ((ull)__float_as_uint(sq0) << 32) | (unsigned)c0;
            ull key1 = ((ull)__float_as_uint(sq1) << 32) | (unsigned)c1;
            while (bal0) {
                int s = __ffs(bal0) - 1; bal0 &= bal0 - 1;
                ull kk = __shfl_sync(0xffffffffu, key0, s);
                ull shv = __shfl_up_sync(0xffffffffu, slot, 1);
                ull ins = (shv > kk) ? shv : kk;
                if (lane == 0) ins = kk;
                if (slot > kk) slot = ins;
            }
            while (bal1) {
                int s = __ffs(bal1) - 1; bal1 &= bal1 - 1;
                ull kk = __shfl_sync(0xffffffffu, key1, s);
                ull shv = __shfl_up_sync(0xffffffffu, slot, 1);
                ull ins = (shv > kk) ? shv : kk;
                if (lane == 0) ins = kk;
                if (slot > kk) slot = ins;
            }
            thr = __uint_as_float(__shfl_sync(0xffffffffu, (unsigned)(slot >> 32), 29));
        }
    }

    if (lane < KNN) {
        float sq = __uint_as_float((unsigned)(slot >> 32));
        int jl = ((int)(unsigned)(slot & 0xffffffffu)) & (NPTS-1);
        bool mask = (nmask[z*NPTS + i] == 0) && (nmask[z*NPTS + jl] == 0)
                    && (sq > 0.f) && (sq < 144.f);          // NaN sentinel fails
        int kf = mask ? jl : i;
        int eidx = (z*NPTS + i)*KNN + lane;
        g_Kidx[eidx] = kf;
        koutf[eidx] = (float)kf;
        moutf[eidx] = mask ? 1.f : 0.f;
    }
}

// --------------------------------------------------------------------------
// 128 edges/block, K split into 2 halves of 128 (atoms {0,1} / {2,3}) so the
// A-operand is 69.6KB -> 2 blocks/SM. Per half: phase A writes RBF straight
// into the compact A layout, then 16 ks8 tf32 mma steps. LN folded epilogue.
__global__ __launch_bounds__(512, 2) void edge_kernel(
        const float* __restrict__ C, const float* __restrict__ centers,
        float* __restrict__ Eout) {
    extern __shared__ float As[];                 // 128*ASTR2
    float* g1s = As + 128*ASTR2;
    float* c0s = g1s + 128;
    float* mus = c0s + 128;
    float* rsg = mus + 128;

    int tid = threadIdx.x;
    if (tid < 128) { g1s[tid] = g_g1[tid]; c0s[tid] = g_c0[tid]; }

    float c0c = __ldg(centers), c15 = __ldg(centers + 15);
    float delta = (c15 - c0c) * (1.f/15.f);
    const float invS2 = 0.64f;
    float invdelta = __fdividef(1.f, delta);
    float sconst = __expf(-2.f*delta*delta*invS2);

    // per-thread edge/geometry setup (invariant over halves)
    int m = tid >> 2, q = tid & 3;
    int e = blockIdx.x*128 + m;
    int z = e / (NPTS*KNN);
    int i = (e - z*(NPTS*KNN)) / KNN;
    int j = g_Kidx[e];
    const float* Cz = C + (size_t)z*NPTS*12;
    int b0 = (q >> 1)*2, a0q = q & 1;
    float bx[2], by[2], bz[2];
#pragma unroll
    for (int bb = 0; bb < 2; ++bb) {
        bx[bb] = Cz[j*12 + (b0+bb)*3 + 0];
        by[bb] = Cz[j*12 + (b0+bb)*3 + 1];
        bz[bb] = Cz[j*12 + (b0+bb)*3 + 2];
    }
    float* Arow = As + m*ASTR2;

    int lane = tid & 31, wid = tid >> 5;
    int rowb = (wid >> 2)*32, nwid = wid & 3;
    int t4 = lane & 3, g4 = lane >> 2;
    float acc[2][4][4];
#pragma unroll
    for (int mf = 0; mf < 2; ++mf)
#pragma unroll
        for (int nf = 0; nf < 4; ++nf)
#pragma unroll
            for (int v = 0; v < 4; ++v) acc[mf][nf][v] = 0.f;

    float sum = 0.f, ssq = 0.f;

#pragma unroll 1
    for (int h = 0; h < 2; ++h) {
        // ---- phase A: atom a = 2h + a0q, neighbors b0, b0+1
        int a = 2*h + a0q;
        float ax = Cz[i*12 + a*3], ay = Cz[i*12 + a*3 + 1], az = Cz[i*12 + a*3 + 2];
#pragma unroll
        for (int bb = 0; bb < 2; ++bb) {
            int pbase = a0q + 2*(b0 + bb);
            float dx = ax - bx[bb], dy = ay - by[bb], dz = az - bz[bb];
            float dsq = dx*dx + dy*dy + dz*dz;
            float d = sqrtf(dsq);
            int mi = __float2int_rn((d - c0c) * invdelta);
            mi = mi < 0 ? 0 : (mi > 15 ? 15 : mi);
            float u = d - fmaf((float)mi, delta, c0c);
            float vm = __expf(-u*u*invS2);
            float gup = __expf((2.f*delta*u - delta*delta)*invS2);
            float hdn = __fdividef(sconst, gup);
            Arow[mi*8 + pbase] = vm;
            sum += vm; ssq = fmaf(vm, vm, ssq);
            float v = vm, rat = gup;
            for (int r = mi+1; r < 16; ++r) {
                v *= rat; rat *= sconst;
                Arow[r*8 + pbase] = v;
                sum += v; ssq = fmaf(v, v, ssq);
            }
            v = vm; rat = hdn;
            for (int r = mi-1; r >= 0; --r) {
                v *= rat; rat *= sconst;
                Arow[r*8 + pbase] = v;
                sum += v; ssq = fmaf(v, v, ssq);
            }
        }
        __syncthreads();

        // ---- GEMM half h: original ks8 = 2*k8 + h
#pragma unroll 4
        for (int k8 = 0; k8 < 16; ++k8) {
            float2 bf[4];
#pragma unroll
            for (int nf = 0; nf < 4; ++nf)
                bf[nf] = __ldg(&g_Bfrag[((k8*2 + h)*16 + nwid*4 + nf)*32 + lane]);
#pragma unroll
            for (int mf = 0; mf < 2; ++mf) {
                int r0 = rowb + mf*16 + g4;
                float2 alo = *(const float2*)&As[r0*ASTR2 + k8*8 + 2*t4];
                float2 ahi = *(const float2*)&As[(r0+8)*ASTR2 + k8*8 + 2*t4];
                uint32_t a0 = __float_as_uint(alo.x), a2 = __float_as_uint(alo.y);
                uint32_t a1 = __float_as_uint(ahi.x), a3 = __float_as_uint(ahi.y);
#pragma unroll
                for (int nf = 0; nf < 4; ++nf)
                    mma8(acc[mf][nf], a0, a1, a2, a3,
                         __float_as_uint(bf[nf].x), __float_as_uint(bf[nf].y));
            }
        }
        __syncthreads();
    }

    // ---- LN stats (sums accumulated across both halves)
    sum += __shfl_xor_sync(0xffffffffu, sum, 1);
    ssq += __shfl_xor_sync(0xffffffffu, ssq, 1);
    sum += __shfl_xor_sync(0xffffffffu, sum, 2);
    ssq += __shfl_xor_sync(0xffffffffu, ssq, 2);
    if (q == 0) {
        float mu = sum * (1.f/256.f);
        float var = ssq * (1.f/256.f) - mu*mu;
        mus[m] = mu;
        rsg[m] = rsqrtf(var + 1e-5f);
    }
    __syncthreads();

    // ---- epilogue: out = rs*(acc - mu*g1) + c0
#pragma unroll
    for (int mf = 0; mf < 2; ++mf) {
        int r0 = rowb + mf*16 + g4;
        float mu0 = mus[r0],   rs0 = rsg[r0];
        float mu1 = mus[r0+8], rs1 = rsg[r0+8];
        float* o0 = Eout + ((size_t)(blockIdx.x*128 + r0))*DMODEL;
        float* o1 = o0 + 8*DMODEL;
#pragma unroll
        for (int nf = 0; nf < 4; ++nf) {
            int col = nwid*32 + nf*8 + 2*t4;
            float ga = g1s[col], gb = g1s[col+1];
            float ca = c0s[col], cb = c0s[col+1];
            float2 v0, v1;
            v0.x = fmaf(rs0, fmaf(-mu0, ga, acc[mf][nf][0]), ca);
            v0.y = fmaf(rs0, fmaf(-mu0, gb, acc[mf][nf][1]), cb);
            v1.x = fmaf(rs1, fmaf(-mu1, ga, acc[mf][nf][2]), ca);
            v1.y = fmaf(rs1, fmaf(-mu1, gb, acc[mf][nf][3]), cb);
            *(float2*)(o0 + col) = v0;
            *(float2*)(o1 + col) = v1;
        }
    }
}

// --------------------------------------------------------------------------
extern "C" void kernel_launch(void* const* d_in, const int* in_sizes, int n_in,
                              void* d_out, int out_size) {
    const float* C       = (const float*)d_in[0];
    const unsigned char* nm = (const unsigned char*)d_in[1];
    const float* centers = (const float*)d_in[2];
    const float* gamma   = (const float*)d_in[3];
    const float* beta    = (const float*)d_in[4];
    const float* W       = (const float*)d_in[5];
    const float* bias    = (const float*)d_in[6];
    float* out = (float*)d_out;
    float* kout = out + (size_t)NEDGE*DMODEL;
    float* mout = kout + NEDGE;

    size_t esm = (size_t)(128*ASTR2 + 4*128) * 4;   // 71680
    size_t ksm = (size_t)NPTS * 16;                 // 65536
    static bool attr_done = false;
    if (!attr_done) {
        cudaFuncSetAttribute(edge_kernel, cudaFuncAttributeMaxDynamicSharedMemorySize, (int)esm);
        cudaFuncSetAttribute(knn_kernel,  cudaFuncAttributeMaxDynamicSharedMemorySize, (int)ksm);
        attr_done = true;
    }

    knn_kernel<<<ZB*(NPTS/KROWS), 32*KROWS, ksm>>>(C, nm, kout, mout);
    prep_kernel<<<9, 1024>>>(W, gamma, beta, bias);
    edge_kernel<<<NEDGE/128, 512, esm>>>(C, centers, out);
}

// round 7
// speedup vs baseline: 11.7384x; 1.0382x over previous
#include <cuda_runtime.h>
#include <cstdint>

#define ZB 2
#define NPTS 4096
#define KNN 30
#define DMODEL 128
#define NEDGE (ZB*NPTS*KNN)
#define ASTR2 136
#define KROWS 32

typedef unsigned long long ull;

__device__ int    g_Kidx[NEDGE];
__device__ float  g_g1[DMODEL];
__device__ float  g_c0[DMODEL];
__device__ float2 g_Bfrag[32*16*32];   // [ks8][nfrag][lane] -> (b0,b1)

__device__ __forceinline__ void mma8(float c[4], uint32_t a0, uint32_t a1, uint32_t a2, uint32_t a3,
                                     uint32_t b0, uint32_t b1) {
    asm("mma.sync.aligned.m16n8k8.row.col.f32.tf32.tf32.f32 "
        "{%0,%1,%2,%3},{%4,%5,%6,%7},{%8,%9},{%0,%1,%2,%3};"
        : "+f"(c[0]), "+f"(c[1]), "+f"(c[2]), "+f"(c[3])
        : "r"(a0), "r"(a1), "r"(a2), "r"(a3), "r"(b0), "r"(b1));
}

// --------------------------------------------------------------------------
__global__ __launch_bounds__(1024) void prep_kernel(
        const float* __restrict__ W, const float* __restrict__ gamma,
        const float* __restrict__ beta, const float* __restrict__ bias) {
    int tid = threadIdx.x;
    if (blockIdx.x < 8) {
#pragma unroll
        for (int u = 0; u < 2; ++u) {
            int p = blockIdx.x*2048 + u*1024 + tid;       // 0..16383
            int lane = p & 31, nf = (p >> 5) & 15, ks8 = p >> 9;
            int n = nf*8 + (lane >> 2);
            float2 v;
#pragma unroll
            for (int h = 0; h < 2; ++h) {
                int t = (lane & 3) + 4*h;                 // mma-local k
                int ksA = ks8*8 + t;
                int kL = (ksA & 15)*16 + (ksA >> 4);      // logical feature row
                float w = W[(size_t)kL*DMODEL + n] * gamma[kL];
                if (h == 0) v.x = w; else v.y = w;
            }
            g_Bfrag[p] = v;
        }
    } else {
        __shared__ float p1[8][DMODEL], p0[8][DMODEL];
        int g = tid >> 7, o = tid & 127;
        float a1 = 0.f, a0 = 0.f;
        int rb = g*32;
#pragma unroll 8
        for (int rr = 0; rr < 32; ++rr) {
            float w = W[(size_t)(rb+rr)*DMODEL + o];
            a1 = fmaf(gamma[rb+rr], w, a1);
            a0 = fmaf(beta[rb+rr],  w, a0);
        }
        p1[g][o] = a1; p0[g][o] = a0;
        __syncthreads();
        if (g == 0) {
            float s1 = 0.f, s0 = 0.f;
#pragma unroll
            for (int k = 0; k < 8; ++k) { s1 += p1[k][o]; s0 += p0[k][o]; }
            g_g1[o] = s1;
            g_c0[o] = s0 + bias[o];
        }
    }
}

// --------------------------------------------------------------------------
// 1 warp/row, warp-distributed top-30. float4 staging (mask folded as NaN),
// float-threshold ballots, deferred threshold refresh, checkless inserts.
__global__ __launch_bounds__(32*KROWS) void knn_kernel(
        const float* __restrict__ C, const unsigned char* __restrict__ nmask,
        float* __restrict__ koutf, float* __restrict__ moutf) {
    extern __shared__ float4 sh4[];            // NPTS
    int z = blockIdx.x / (NPTS/KROWS);
    int rowbase = (blockIdx.x % (NPTS/KROWS)) * KROWS;
    const float4* Cz4 = (const float4*)(C + (size_t)z*NPTS*12);
    for (int p = threadIdx.x; p < NPTS; p += 32*KROWS) {
        float4 a = Cz4[3*p], b = Cz4[3*p + 1];     // Ca = floats 3,4,5
        float x = a.w;
        if (nmask[z*NPTS + p]) x = __int_as_float(0x7fffffff);   // NaN-fold mask
        sh4[p] = make_float4(x, b.x, b.y, 0.f);
    }
    __syncthreads();
    int w = threadIdx.x >> 5, lane = threadIdx.x & 31;
    int i = rowbase + w;
    float4 qv = sh4[i];
    float qx = qv.x, qy = qv.y, qz = qv.z;

    ull slot = ~0ull;                              // lane L: rank-L key
    float thr = __uint_as_float(0xFFFFFFFFu);      // NaN: !(sq>thr) passes all

#pragma unroll 1
    for (int kb = 0; kb < NPTS/64; ++kb) {
        int c0 = kb*64 + lane, c1 = c0 + 32;
        float4 p0 = sh4[c0], p1 = sh4[c1];
        float dx0 = __fsub_rn(p0.x, qx), dy0 = __fsub_rn(p0.y, qy), dz0 = __fsub_rn(p0.z, qz);
        float dx1 = __fsub_rn(p1.x, qx), dy1 = __fsub_rn(p1.y, qy), dz1 = __fsub_rn(p1.z, qz);
        float sq0 = __fadd_rn(__fadd_rn(__fmul_rn(dx0,dx0), __fmul_rn(dy0,dy0)), __fmul_rn(dz0,dz0));
        float sq1 = __fadd_rn(__fadd_rn(__fmul_rn(dx1,dx1), __fmul_rn(dy1,dy1)), __fmul_rn(dz1,dz1));
        unsigned bal0 = __ballot_sync(0xffffffffu, (sq0 > 0.f) && !(sq0 > thr));
        unsigned bal1 = __ballot_sync(0xffffffffu, (sq1 > 0.f) && !(sq1 > thr));
        if (bal0 | bal1) {
            ull key0 = ((ull)__float_as_uint(sq0) << 32) | (unsigned)c0;
            ull key1 = ((ull)__float_as_uint(sq1) << 32) | (unsigned)c1;
            while (bal0) {
                int s = __ffs(bal0) - 1; bal0 &= bal0 - 1;
                ull kk = __shfl_sync(0xffffffffu, key0, s);
                ull shv = __shfl_up_sync(0xffffffffu, slot, 1);
                ull ins = (shv > kk) ? shv : kk;
                if (lane == 0) ins = kk;
                if (slot > kk) slot = ins;
            }
            while (bal1) {
                int s = __ffs(bal1) - 1; bal1 &= bal1 - 1;
                ull kk = __shfl_sync(0xffffffffu, key1, s);
                ull shv = __shfl_up_sync(0xffffffffu, slot, 1);
                ull ins = (shv > kk) ? shv : kk;
                if (lane == 0) ins = kk;
                if (slot > kk) slot = ins;
            }
            thr = __uint_as_float(__shfl_sync(0xffffffffu, (unsigned)(slot >> 32), 29));
        }
    }

    if (lane < KNN) {
        float sq = __uint_as_float((unsigned)(slot >> 32));
        int jl = ((int)(unsigned)(slot & 0xffffffffu)) & (NPTS-1);
        bool mask = (nmask[z*NPTS + i] == 0) && (nmask[z*NPTS + jl] == 0)
                    && (sq > 0.f) && (sq < 144.f);          // NaN sentinel fails
        int kf = mask ? jl : i;
        int eidx = (z*NPTS + i)*KNN + lane;
        g_Kidx[eidx] = kf;
        koutf[eidx] = (float)kf;
        moutf[eidx] = mask ? 1.f : 0.f;
    }
}

// --------------------------------------------------------------------------
// 128 edges/block, K split into 2 halves (atoms {0,1} / {2,3}); A-operand
// 69.6KB -> 2 blocks/SM. acc init deferred past phase A h=0 and coords
// reloaded per half to keep regs under the 64-reg cap (no spills).
__global__ __launch_bounds__(512, 2) void edge_kernel(
        const float* __restrict__ C, const float* __restrict__ centers,
        float* __restrict__ Eout) {
    extern __shared__ float As[];                 // 128*ASTR2
    float* g1s = As + 128*ASTR2;
    float* c0s = g1s + 128;
    float* mus = c0s + 128;
    float* rsg = mus + 128;

    int tid = threadIdx.x;
    if (tid < 128) { g1s[tid] = g_g1[tid]; c0s[tid] = g_c0[tid]; }

    float c0c = __ldg(centers), c15 = __ldg(centers + 15);
    float delta = (c15 - c0c) * (1.f/15.f);
    const float invS2 = 0.64f;
    float invdelta = __fdividef(1.f, delta);
    float sconst = __expf(-2.f*delta*delta*invS2);

    int m = tid >> 2, q = tid & 3;
    int e = blockIdx.x*128 + m;
    int z = e / (NPTS*KNN);
    int i = (e - z*(NPTS*KNN)) / KNN;
    const float* pi = C + (size_t)z*NPTS*12 + (size_t)i*12;
    const float* pj = C + (size_t)z*NPTS*12 + (size_t)g_Kidx[e]*12;
    float* Arow = As + m*ASTR2;
    int b0 = (q >> 1)*2, a0q = q & 1;

    int lane = tid & 31, wid = tid >> 5;
    int rowb = (wid >> 2)*32, nwid = wid & 3;
    int t4 = lane & 3, g4 = lane >> 2;
    float acc[2][4][4];
    float sum = 0.f, ssq = 0.f;

#pragma unroll 1
    for (int h = 0; h < 2; ++h) {
        // ---- phase A: atom a = 2h + a0q vs neighbor atoms b0, b0+1
        {
            int a = 2*h + a0q;
            float ax = pi[a*3], ay = pi[a*3 + 1], az = pi[a*3 + 2];
#pragma unroll
            for (int bb = 0; bb < 2; ++bb) {
                int pbase = a0q + 2*(b0 + bb);
                float dx = ax - pj[(b0+bb)*3 + 0];
                float dy = ay - pj[(b0+bb)*3 + 1];
                float dz = az - pj[(b0+bb)*3 + 2];
                float dsq = dx*dx + dy*dy + dz*dz;
                float d = sqrtf(dsq);
                int mi = __float2int_rn((d - c0c) * invdelta);
                mi = mi < 0 ? 0 : (mi > 15 ? 15 : mi);
                float u = d - fmaf((float)mi, delta, c0c);
                float vm = __expf(-u*u*invS2);
                float gup = __expf((2.f*delta*u - delta*delta)*invS2);
                float hdn = __fdividef(sconst, gup);
                Arow[mi*8 + pbase] = vm;
                sum += vm; ssq = fmaf(vm, vm, ssq);
                float v = vm, rat = gup;
                for (int r = mi+1; r < 16; ++r) {
                    v *= rat; rat *= sconst;
                    Arow[r*8 + pbase] = v;
                    sum += v; ssq = fmaf(v, v, ssq);
                }
                v = vm; rat = hdn;
                for (int r = mi-1; r >= 0; --r) {
                    v *= rat; rat *= sconst;
                    Arow[r*8 + pbase] = v;
                    sum += v; ssq = fmaf(v, v, ssq);
                }
            }
        }
        if (h == 0) {
#pragma unroll
            for (int mf = 0; mf < 2; ++mf)
#pragma unroll
                for (int nf = 0; nf < 4; ++nf)
#pragma unroll
                    for (int v = 0; v < 4; ++v) acc[mf][nf][v] = 0.f;
        }
        __syncthreads();
        if (h == 1) {
            // LN stats: sums complete after phase A h=1; store hides behind GEMM
            sum += __shfl_xor_sync(0xffffffffu, sum, 1);
            ssq += __shfl_xor_sync(0xffffffffu, ssq, 1);
            sum += __shfl_xor_sync(0xffffffffu, sum, 2);
            ssq += __shfl_xor_sync(0xffffffffu, ssq, 2);
            if (q == 0) {
                float mu = sum * (1.f/256.f);
                float var = ssq * (1.f/256.f) - mu*mu;
                mus[m] = mu;
                rsg[m] = rsqrtf(var + 1e-5f);
            }
        }

        // ---- GEMM half h: original ks8 = 2*k8 + h
#pragma unroll 2
        for (int k8 = 0; k8 < 16; ++k8) {
            float2 bf[4];
#pragma unroll
            for (int nf = 0; nf < 4; ++nf)
                bf[nf] = __ldg(&g_Bfrag[((k8*2 + h)*16 + nwid*4 + nf)*32 + lane]);
#pragma unroll
            for (int mf = 0; mf < 2; ++mf) {
                int r0 = rowb + mf*16 + g4;
                float2 alo = *(const float2*)&As[r0*ASTR2 + k8*8 + 2*t4];
                float2 ahi = *(const float2*)&As[(r0+8)*ASTR2 + k8*8 + 2*t4];
                uint32_t a0 = __float_as_uint(alo.x), a2 = __float_as_uint(alo.y);
                uint32_t a1 = __float_as_uint(ahi.x), a3 = __float_as_uint(ahi.y);
#pragma unroll
                for (int nf = 0; nf < 4; ++nf)
                    mma8(acc[mf][nf], a0, a1, a2, a3,
                         __float_as_uint(bf[nf].x), __float_as_uint(bf[nf].y));
            }
        }
        __syncthreads();
    }

    // ---- epilogue: out = rs*(acc - mu*g1) + c0
#pragma unroll
    for (int mf = 0; mf < 2; ++mf) {
        int r0 = rowb + mf*16 + g4;
        float mu0 = mus[r0],   rs0 = rsg[r0];
        float mu1 = mus[r0+8], rs1 = rsg[r0+8];
        float* o0 = Eout + ((size_t)(blockIdx.x*128 + r0))*DMODEL;
        float* o1 = o0 + 8*DMODEL;
#pragma unroll
        for (int nf = 0; nf < 4; ++nf) {
            int col = nwid*32 + nf*8 + 2*t4;
            float ga = g1s[col], gb = g1s[col+1];
            float ca = c0s[col], cb = c0s[col+1];
            float2 v0, v1;
            v0.x = fmaf(rs0, fmaf(-mu0, ga, acc[mf][nf][0]), ca);
            v0.y = fmaf(rs0, fmaf(-mu0, gb, acc[mf][nf][1]), cb);
            v1.x = fmaf(rs1, fmaf(-mu1, ga, acc[mf][nf][2]), ca);
            v1.y = fmaf(rs1, fmaf(-mu1, gb, acc[mf][nf][3]), cb);
            *(float2*)(o0 + col) = v0;
            *(float2*)(o1 + col) = v1;
        }
    }
}

// --------------------------------------------------------------------------
extern "C" void kernel_launch(void* const* d_in, const int* in_sizes, int n_in,
                              void* d_out, int out_size) {
    const float* C       = (const float*)d_in[0];
    const unsigned char* nm = (const unsigned char*)d_in[1];
    const float* centers = (const float*)d_in[2];
    const float* gamma   = (const float*)d_in[3];
    const float* beta    = (const float*)d_in[4];
    const float* W       = (const float*)d_in[5];
    const float* bias    = (const float*)d_in[6];
    float* out = (float*)d_out;
    float* kout = out + (size_t)NEDGE*DMODEL;
    float* mout = kout + NEDGE;

    size_t esm = (size_t)(128*ASTR2 + 4*128) * 4;   // 71680
    size_t ksm = (size_t)NPTS * 16;                 // 65536
    static bool attr_done = false;
    if (!attr_done) {
        cudaFuncSetAttribute(edge_kernel, cudaFuncAttributeMaxDynamicSharedMemorySize, (int)esm);
        cudaFuncSetAttribute(knn_kernel,  cudaFuncAttributeMaxDynamicSharedMemorySize, (int)ksm);
        attr_done = true;
    }

    knn_kernel<<<ZB*(NPTS/KROWS), 32*KROWS, ksm>>>(C, nm, kout, mout);
    prep_kernel<<<9, 1024>>>(W, gamma, beta, bias);
    edge_kernel<<<NEDGE/128, 512, esm>>>(C, centers, out);
}

// round 9
// speedup vs baseline: 14.0880x; 1.2002x over previous
#include <cuda_runtime.h>
#include <cstdint>

#define ZB 2
#define NPTS 4096
#define KNN 30
#define DMODEL 128
#define NEDGE (ZB*NPTS*KNN)
#define ASTRA 72
#define KROWS 32

typedef unsigned long long ull;

__device__ int    g_Kidx[NEDGE];
__device__ float  g_g1[DMODEL];
__device__ float  g_c0[DMODEL];
__device__ float2 g_Bfrag[4*8*16*32];   // [qt][k8q][nf][lane] -> (b0,b1)

__device__ __forceinline__ void mma8(float c[4], uint32_t a0, uint32_t a1, uint32_t a2, uint32_t a3,
                                     uint32_t b0, uint32_t b1) {
    asm("mma.sync.aligned.m16n8k8.row.col.f32.tf32.tf32.f32 "
        "{%0,%1,%2,%3},{%4,%5,%6,%7},{%8,%9},{%0,%1,%2,%3};"
        : "+f"(c[0]), "+f"(c[1]), "+f"(c[2]), "+f"(c[3])
        : "r"(a0), "r"(a1), "r"(a2), "r"(a3), "r"(b0), "r"(b1));
}

// --------------------------------------------------------------------------
// blocks 0-7: g_Bfrag[qt][k8q][nf][lane]; block 8: g1/c0 fold.
// mma-k t reads A phys offset f(t)=2*(t&3)+(t>>2) within each 8-block
// (a0=alo.x, a2=alo.y pairing) -> B logical must follow the same map.
__global__ __launch_bounds__(1024) void prep_kernel(
        const float* __restrict__ W, const float* __restrict__ gamma,
        const float* __restrict__ beta, const float* __restrict__ bias) {
    int tid = threadIdx.x;
    if (blockIdx.x < 8) {
#pragma unroll
        for (int u = 0; u < 2; ++u) {
            int p = blockIdx.x*2048 + u*1024 + tid;       // 0..16383
            int lane = p & 31, nf = (p >> 5) & 15, k8q = (p >> 9) & 7, qt = p >> 12;
            int n = nf*8 + (lane >> 2);
            float2 v;
#pragma unroll
            for (int h = 0; h < 2; ++h) {
                int t = (lane & 3) + 4*h;                 // mma-local k
                int fo = 2*(t & 3) + (t >> 2);            // phys offset read by A frag
                int p4 = k8q*8 + fo;                      // phys k within quarter
                int r = p4 >> 2, b = p4 & 3;              // phase A: phys = 4r + b
                int kL = (qt*4 + b)*16 + r;               // logical feature row
                float w = W[(size_t)kL*DMODEL + n] * gamma[kL];
                if (h == 0) v.x = w; else v.y = w;
            }
            g_Bfrag[p] = v;
        }
    } else {
        __shared__ float p1[8][DMODEL], p0[8][DMODEL];
        int g = tid >> 7, o = tid & 127;
        float a1 = 0.f, a0 = 0.f;
        int rb = g*32;
#pragma unroll 8
        for (int rr = 0; rr < 32; ++rr) {
            float w = W[(size_t)(rb+rr)*DMODEL + o];
            a1 = fmaf(gamma[rb+rr], w, a1);
            a0 = fmaf(beta[rb+rr],  w, a0);
        }
        p1[g][o] = a1; p0[g][o] = a0;
        __syncthreads();
        if (g == 0) {
            float s1 = 0.f, s0 = 0.f;
#pragma unroll
            for (int k = 0; k < 8; ++k) { s1 += p1[k][o]; s0 += p0[k][o]; }
            g_g1[o] = s1;
            g_c0[o] = s0 + bias[o];
        }
    }
}

// --------------------------------------------------------------------------
// 1 warp/row, warp-distributed top-30 with 32-bit (sq,idx) slot pairs.
__global__ __launch_bounds__(32*KROWS) void knn_kernel(
        const float* __restrict__ C, const unsigned char* __restrict__ nmask,
        float* __restrict__ koutf, float* __restrict__ moutf) {
    extern __shared__ float4 sh4[];            // NPTS
    int z = blockIdx.x / (NPTS/KROWS);
    int rowbase = (blockIdx.x % (NPTS/KROWS)) * KROWS;
    const float4* Cz4 = (const float4*)(C + (size_t)z*NPTS*12);
    for (int p = threadIdx.x; p < NPTS; p += 32*KROWS) {
        float4 a = Cz4[3*p], b = Cz4[3*p + 1];     // Ca = floats 3,4,5
        float x = a.w;
        if (nmask[z*NPTS + p]) x = __int_as_float(0x7fffffff);   // NaN-fold mask
        sh4[p] = make_float4(x, b.x, b.y, 0.f);
    }
    __syncthreads();
    int w = threadIdx.x >> 5, lane = threadIdx.x & 31;
    int i = rowbase + w;
    float4 qv = sh4[i];
    float qx = qv.x, qy = qv.y, qz = qv.z;

    unsigned slot_sq = 0xFFFFFFFFu;            // lane L: rank-L sq bits
    unsigned slot_idx = (unsigned)i;
    unsigned thrb = 0xFFFFFFFFu;

#pragma unroll 1
    for (int kb = 0; kb < NPTS/64; ++kb) {
        float4 p0 = sh4[kb*64 + lane], p1 = sh4[kb*64 + 32 + lane];
        float dx0 = __fsub_rn(p0.x, qx), dy0 = __fsub_rn(p0.y, qy), dz0 = __fsub_rn(p0.z, qz);
        float dx1 = __fsub_rn(p1.x, qx), dy1 = __fsub_rn(p1.y, qy), dz1 = __fsub_rn(p1.z, qz);
        float sq0 = __fadd_rn(__fadd_rn(__fmul_rn(dx0,dx0), __fmul_rn(dy0,dy0)), __fmul_rn(dz0,dz0));
        float sq1 = __fadd_rn(__fadd_rn(__fmul_rn(dx1,dx1), __fmul_rn(dy1,dy1)), __fmul_rn(dz1,dz1));
        unsigned q0 = __float_as_uint(sq0), q1 = __float_as_uint(sq1);
        unsigned bal0 = __ballot_sync(0xffffffffu, (sq0 > 0.f) && (q0 < thrb));
        unsigned bal1 = __ballot_sync(0xffffffffu, (sq1 > 0.f) && (q1 < thrb));
        if (bal0 | bal1) {
            while (bal0) {
                int s = __ffs(bal0) - 1; bal0 &= bal0 - 1;
                unsigned ksq = __shfl_sync(0xffffffffu, q0, s);
                unsigned kidx = (unsigned)(kb*64 + s);
                unsigned squp = __shfl_up_sync(0xffffffffu, slot_sq, 1);
                unsigned idup = __shfl_up_sync(0xffffffffu, slot_idx, 1);
                bool up = (squp > ksq) && (lane != 0);
                if (slot_sq > ksq) { slot_sq = up ? squp : ksq; slot_idx = up ? idup : kidx; }
            }
            while (bal1) {
                int s = __ffs(bal1) - 1; bal1 &= bal1 - 1;
                unsigned ksq = __shfl_sync(0xffffffffu, q1, s);
                unsigned kidx = (unsigned)(kb*64 + 32 + s);
                unsigned squp = __shfl_up_sync(0xffffffffu, slot_sq, 1);
                unsigned idup = __shfl_up_sync(0xffffffffu, slot_idx, 1);
                bool up = (squp > ksq) && (lane != 0);
                if (slot_sq > ksq) { slot_sq = up ? squp : ksq; slot_idx = up ? idup : kidx; }
            }
            thrb = __shfl_sync(0xffffffffu, slot_sq, 29);
        }
    }

    if (lane < KNN) {
        float sq = __uint_as_float(slot_sq);
        int jl = (int)slot_idx;
        bool mask = (nmask[z*NPTS + i] == 0) && (nmask[z*NPTS + jl] == 0)
                    && (sq > 0.f) && (sq < 144.f);          // NaN sentinel fails
        int kf = mask ? jl : i;
        int eidx = (z*NPTS + i)*KNN + lane;
        g_Kidx[eidx] = kf;
        koutf[eidx] = (float)kf;
        moutf[eidx] = mask ? 1.f : 0.f;
    }
}

// --------------------------------------------------------------------------
// 128 edges/block, K split into 4 quarters (query atom qt each). A 36.9KB +
// B-quarter 32KB staged in smem (B read from L2 once/block) -> 2 blocks/SM,
// GEMM inner loop pure LDS+HMMA. LN folded epilogue.
__global__ __launch_bounds__(512, 2) void edge_kernel(
        const float* __restrict__ C, const float* __restrict__ centers,
        float* __restrict__ Eout) {
    extern __shared__ float As[];                 // 128*ASTRA
    float* Bs  = As + 128*ASTRA;                  // 8192 floats (32KB)
    float* g1s = Bs + 8192;
    float* c0s = g1s + 128;
    float* mus = c0s + 128;
    float* rsg = mus + 128;

    int tid = threadIdx.x;
    if (tid < 128) { g1s[tid] = g_g1[tid]; c0s[tid] = g_c0[tid]; }

    float c0c = __ldg(centers), c15 = __ldg(centers + 15);
    float delta = (c15 - c0c) * (1.f/15.f);
    const float invS2 = 0.64f;
    float invdelta = __fdividef(1.f, delta);
    float sconst = __expf(-2.f*delta*delta*invS2);

    int m = tid >> 2, q = tid & 3;                // thread q = neighbor atom b
    int e = blockIdx.x*128 + m;
    int z = e / (NPTS*KNN);
    int i = (e - z*(NPTS*KNN)) / KNN;
    const float* pi = C + (size_t)z*NPTS*12 + (size_t)i*12;
    const float* pj = C + (size_t)z*NPTS*12 + (size_t)g_Kidx[e]*12;
    float bxc = pj[q*3], byc = pj[q*3 + 1], bzc = pj[q*3 + 2];
    float* Arow = As + m*ASTRA;

    int lane = tid & 31, wid = tid >> 5;
    int rowb = (wid >> 2)*32, nwid = wid & 3;
    int t4 = lane & 3, g4 = lane >> 2;
    float acc[2][4][4];
#pragma unroll
    for (int mf = 0; mf < 2; ++mf)
#pragma unroll
        for (int nf = 0; nf < 4; ++nf)
#pragma unroll
            for (int v = 0; v < 4; ++v) acc[mf][nf][v] = 0.f;
    float sum = 0.f, ssq = 0.f;

#pragma unroll 1
    for (int qt = 0; qt < 4; ++qt) {
        if (qt) __syncthreads();                  // prev GEMM done reading
        // ---- B fill: quarter table 4096 float2 = 2048 float4
        {
            const float4* src = (const float4*)(g_Bfrag + qt*4096);
            float4* dst = (float4*)Bs;
#pragma unroll
            for (int u = 0; u < 4; ++u) dst[u*512 + tid] = src[u*512 + tid];
        }
        // ---- phase A: dist(i atom qt, j atom q) -> 16 rbf at As[m][r*4+q]
        {
            float ax = pi[qt*3], ay = pi[qt*3 + 1], az = pi[qt*3 + 2];
            float dx = ax - bxc, dy = ay - byc, dz = az - bzc;
            float dsq = dx*dx + dy*dy + dz*dz;
            float d = sqrtf(dsq);
            int mi = __float2int_rn((d - c0c) * invdelta);
            mi = mi < 0 ? 0 : (mi > 15 ? 15 : mi);
            float u = d - fmaf((float)mi, delta, c0c);
            float vm = __expf(-u*u*invS2);
            float gup = __expf((2.f*delta*u - delta*delta)*invS2);
            float hdn = __fdividef(sconst, gup);
            Arow[mi*4 + q] = vm;
            sum += vm; ssq = fmaf(vm, vm, ssq);
            float v = vm, rat = gup;
            for (int r = mi+1; r < 16; ++r) {
                v *= rat; rat *= sconst;
                Arow[r*4 + q] = v;
                sum += v; ssq = fmaf(v, v, ssq);
            }
            v = vm; rat = hdn;
            for (int r = mi-1; r >= 0; --r) {
                v *= rat; rat *= sconst;
                Arow[r*4 + q] = v;
                sum += v; ssq = fmaf(v, v, ssq);
            }
        }
        if (qt == 3) {
            sum += __shfl_xor_sync(0xffffffffu, sum, 1);
            ssq += __shfl_xor_sync(0xffffffffu, ssq, 1);
            sum += __shfl_xor_sync(0xffffffffu, sum, 2);
            ssq += __shfl_xor_sync(0xffffffffu, ssq, 2);
            if (q == 0) {
                float mu = sum * (1.f/256.f);
                float var = ssq * (1.f/256.f) - mu*mu;
                mus[m] = mu;
                rsg[m] = rsqrtf(var + 1e-5f);
            }
        }
        __syncthreads();

        // ---- GEMM quarter: 8 k8q steps, B from smem
#pragma unroll 2
        for (int k8q = 0; k8q < 8; ++k8q) {
            float2 bf[4];
#pragma unroll
            for (int nf = 0; nf < 4; ++nf)
                bf[nf] = *(const float2*)&Bs[((k8q*16 + nwid*4 + nf)*32 + lane)*2];
#pragma unroll
            for (int mf = 0; mf < 2; ++mf) {
                int r0 = rowb + mf*16 + g4;
                float2 alo = *(const float2*)&As[r0*ASTRA + k8q*8 + 2*t4];
                float2 ahi = *(const float2*)&As[(r0+8)*ASTRA + k8q*8 + 2*t4];
                uint32_t a0 = __float_as_uint(alo.x), a2 = __float_as_uint(alo.y);
                uint32_t a1 = __float_as_uint(ahi.x), a3 = __float_as_uint(ahi.y);
#pragma unroll
                for (int nf = 0; nf < 4; ++nf)
                    mma8(acc[mf][nf], a0, a1, a2, a3,
                         __float_as_uint(bf[nf].x), __float_as_uint(bf[nf].y));
            }
        }
    }

    // ---- epilogue: out = rs*(acc - mu*g1) + c0
#pragma unroll
    for (int mf = 0; mf < 2; ++mf) {
        int r0 = rowb + mf*16 + g4;
        float mu0 = mus[r0],   rs0 = rsg[r0];
        float mu1 = mus[r0+8], rs1 = rsg[r0+8];
        float* o0 = Eout + ((size_t)(blockIdx.x*128 + r0))*DMODEL;
        float* o1 = o0 + 8*DMODEL;
#pragma unroll
        for (int nf = 0; nf < 4; ++nf) {
            int col = nwid*32 + nf*8 + 2*t4;
            float ga = g1s[col], gb = g1s[col+1];
            float ca = c0s[col], cb = c0s[col+1];
            float2 v0, v1;
            v0.x = fmaf(rs0, fmaf(-mu0, ga, acc[mf][nf][0]), ca);
            v0.y = fmaf(rs0, fmaf(-mu0, gb, acc[mf][nf][1]), cb);
            v1.x = fmaf(rs1, fmaf(-mu1, ga, acc[mf][nf][2]), ca);
            v1.y = fmaf(rs1, fmaf(-mu1, gb, acc[mf][nf][3]), cb);
            *(float2*)(o0 + col) = v0;
            *(float2*)(o1 + col) = v1;
        }
    }
}

// --------------------------------------------------------------------------
extern "C" void kernel_launch(void* const* d_in, const int* in_sizes, int n_in,
                              void* d_out, int out_size) {
    const float* C       = (const float*)d_in[0];
    const unsigned char* nm = (const unsigned char*)d_in[1];
    const float* centers = (const float*)d_in[2];
    const float* gamma   = (const float*)d_in[3];
    const float* beta    = (const float*)d_in[4];
    const float* W       = (const float*)d_in[5];
    const float* bias    = (const float*)d_in[6];
    float* out = (float*)d_out;
    float* kout = out + (size_t)NEDGE*DMODEL;
    float* mout = kout + NEDGE;

    size_t esm = (size_t)(128*ASTRA + 8192 + 4*128) * 4;   // 71680
    size_t ksm = (size_t)NPTS * 16;                        // 65536
    static bool attr_done = false;
    if (!attr_done) {
        cudaFuncSetAttribute(edge_kernel, cudaFuncAttributeMaxDynamicSharedMemorySize, (int)esm);
        cudaFuncSetAttribute(knn_kernel,  cudaFuncAttributeMaxDynamicSharedMemorySize, (int)ksm);
        attr_done = true;
    }

    knn_kernel<<<ZB*(NPTS/KROWS), 32*KROWS, ksm>>>(C, nm, kout, mout);
    prep_kernel<<<9, 1024>>>(W, gamma, beta, bias);
    edge_kernel<<<NEDGE/128, 512, esm>>>(C, centers, out);
}